// round 10
// baseline (speedup 1.0000x reference)
#include <cuda_runtime.h>
#include <stdint.h>
#include <math.h>

#define Bv 16
#define Hv 512
#define Wv 512
#define NPLANES 48

// Scratch (device globals -- no runtime allocation allowed)
__device__ uint32_t g_weakbits[NPLANES * Hv * 16];    // 16 u32 words per row
__device__ uint32_t g_strongbits[NPLANES * Hv * 16];

// ---------------- scalar error-free compensated summation --------------------
__device__ __forceinline__ void two_sum(float a, float b, float& s, float& e) {
    s = __fadd_rn(a, b);
    float bb = __fsub_rn(s, a);
    e = __fadd_rn(__fsub_rn(a, __fsub_rn(s, bb)), __fsub_rn(b, bb));
}

template <int N>
__device__ __forceinline__ float sum_exact(const float* t) {
    float s = t[0], e = 0.f;
#pragma unroll
    for (int i = 1; i < N; ++i) {
        float ei;
        two_sum(s, t[i], s, ei);
        e = __fadd_rn(e, ei);
    }
    return __fadd_rn(s, e);
}

// ---------------- packed f32x2 primitives (per-lane IEEE RN: bit-identical) --
__device__ __forceinline__ uint64_t pk2(float lo, float hi) {
    uint64_t r; asm("mov.b64 %0, {%1,%2};" : "=l"(r) : "f"(lo), "f"(hi)); return r;
}
__device__ __forceinline__ void upk2(uint64_t v, float& lo, float& hi) {
    asm("mov.b64 {%0,%1}, %2;" : "=f"(lo), "=f"(hi) : "l"(v));
}
__device__ __forceinline__ uint64_t dupc(float w) {
    uint32_t u = __float_as_uint(w);
    return ((uint64_t)u << 32) | u;
}
__device__ __forceinline__ uint64_t add2(uint64_t a, uint64_t b) {
    uint64_t r; asm("add.rn.f32x2 %0, %1, %2;" : "=l"(r) : "l"(a), "l"(b)); return r;
}
__device__ __forceinline__ uint64_t mul2(uint64_t a, uint64_t b) {
    uint64_t r; asm("mul.rn.f32x2 %0, %1, %2;" : "=l"(r) : "l"(a), "l"(b)); return r;
}
__device__ __forceinline__ uint64_t fma2(uint64_t a, uint64_t b, uint64_t c) {
    uint64_t r; asm("fma.rn.f32x2 %0, %1, %2, %3;" : "=l"(r) : "l"(a), "l"(b), "l"(c)); return r;
}
// exact: fma(b,-1,a) rounds a-b once -> identical to sub.rn per lane
__device__ __forceinline__ uint64_t sub2(uint64_t a, uint64_t b) {
    return fma2(b, 0xBF800000BF800000ULL, a);
}
__device__ __forceinline__ uint64_t neg2(uint64_t a) {        // exact negation
    return mul2(a, 0xBF800000BF800000ULL);
}
__device__ __forceinline__ void two_sum2(uint64_t a, uint64_t b, uint64_t& s, uint64_t& e) {
    s = add2(a, b);
    uint64_t bb = sub2(s, a);
    uint64_t t1 = sub2(s, bb);
    uint64_t t2 = sub2(a, t1);
    uint64_t t3 = sub2(b, bb);
    e = add2(t2, t3);
}
template <int N>
__device__ __forceinline__ uint64_t sum_exact2(const uint64_t* t) {
    uint64_t s = t[0], e = 0ULL;   // 0.0f packed
#pragma unroll
    for (int i = 1; i < N; ++i) {
        uint64_t ei;
        two_sum2(s, t[i], s, ei);
        e = add2(e, ei);
    }
    return add2(s, e);
}

// load 4 consecutive floats (8B-aligned) -> tap pairs A=(v0,v1) B=(v1,v2) C=(v2,v3)
__device__ __forceinline__ void load3(const float* p, uint64_t& A, uint64_t& B, uint64_t& C) {
    A = *(const uint64_t*)p;
    C = *(const uint64_t*)(p + 2);
    float a0, a1, c0, c1;
    upk2(A, a0, a1);
    upk2(C, c0, c1);
    B = pk2(a1, c0);
}

// ---------------- sector from slopes (no atan2; boundaries from 180/3.14159) -
#define SEC_T1  0.41421317f
#define SEC_T2  2.4142068f
#define SEC_TP3 2.4142249f
#define SEC_TP4 0.41421628f

__device__ __forceinline__ uint8_t sector_of(float gx, float gy) {
    if (gy >= 0.f) {
        if (gx > 0.f)  return (gy <= SEC_T1 * gx) ? 0 : ((gy <= SEC_T2 * gx) ? 1 : 2);
        if (gx < 0.f) { float a = -gx;
                        return (gy < SEC_TP4 * a) ? 0 : ((gy < SEC_TP3 * a) ? 3 : 2); }
        return (gy > 0.f) ? 2 : 0;
    } else {
        float g = -gy;
        if (gx > 0.f)  return (g < SEC_T1 * gx) ? 0 : ((g < SEC_T2 * gx) ? 3 : 2);
        if (gx < 0.f) { float a = -gx;
                        return (g <= SEC_TP4 * a) ? 0 : ((g <= SEC_TP3 * a) ? 1 : 2); }
        return 2;
    }
}

// ========== K1: blur + sobel + mag + sector + NMS + threshold (fused) ========
#define SW 40   // smem row stride (floats); even -> 8B-aligned pair addresses

__device__ __forceinline__ void sobel_masked(const float* sb, int bi,
                                             bool ym, bool yp, bool xm, bool xp,
                                             float& gx, float& gy) {
    float v00 = (ym && xm) ? sb[bi - SW - 1] : 0.f;
    float v01 =  ym        ? sb[bi - SW]     : 0.f;
    float v02 = (ym && xp) ? sb[bi - SW + 1] : 0.f;
    float v10 =  xm        ? sb[bi - 1]      : 0.f;
    float v12 =  xp        ? sb[bi + 1]      : 0.f;
    float v20 = (yp && xm) ? sb[bi + SW - 1] : 0.f;
    float v21 =  yp        ? sb[bi + SW]     : 0.f;
    float v22 = (yp && xp) ? sb[bi + SW + 1] : 0.f;
    float tx[6] = { -v00, v02, __fmul_rn(-2.f, v10), __fmul_rn(2.f, v12), -v20, v22 };
    gx = sum_exact<6>(tx);
    float ty[6] = { -v00, __fmul_rn(-2.f, v01), -v02, v20, __fmul_rn(2.f, v21), v22 };
    gy = sum_exact<6>(ty);
}

__device__ __forceinline__ float mag_of(float gx, float gy) {
    float s = __fadd_rn(__fmul_rn(gx, gx), __fmul_rn(gy, gy));
    return __fsqrt_rn(s);
}

// packed sobel taps from preloaded row pairs (same tap order as scalar)
__device__ __forceinline__ void sobel_pair(uint64_t A0, uint64_t B0, uint64_t C0,
                                           uint64_t A1,              uint64_t C1,
                                           uint64_t A2, uint64_t B2, uint64_t C2,
                                           uint64_t M2, uint64_t P2,
                                           uint64_t& gxp, uint64_t& gyp) {
    uint64_t tx[6] = { neg2(A0), C0, mul2(A1, M2), mul2(C1, P2), neg2(A2), C2 };
    gxp = sum_exact2<6>(tx);
    uint64_t ty[6] = { neg2(A0), mul2(B0, M2), neg2(C0), A2, mul2(B2, P2), C2 };
    gyp = sum_exact2<6>(ty);
}

__global__ void __launch_bounds__(256) canny_k(const float* __restrict__ x) {
    __shared__ __align__(16) float   si[38 * SW];   // input  rows y0-3..y0+34 (toroidal)
    __shared__ __align__(16) float   sl[36 * SW];   // blur   y0-2..y0+33
    __shared__ __align__(16) float   sm[34 * SW];   // mag    y0-1..y0+32
    __shared__ uint8_t ssec[32 * 32];               // sector of inner pixels
    int tid  = threadIdx.x;
    int lane = tid & 31;
    int warp = tid >> 5;
    int plane = blockIdx.x;                 // b*3+c (fastest -> channel L2 reuse)
    int x0 = blockIdx.y * 32;
    int y0 = blockIdx.z * 32;
    int b = plane / 3, c = plane - 3 * b;
    const float* base = x + (size_t)b * (Hv * Wv * 3) + c;

    bool border = (blockIdx.y == 0) || (blockIdx.y == 15) ||
                  (blockIdx.z == 0) || (blockIdx.z == 15);

    // ---- load 38x38 input (toroidal; interior blocks never actually wrap) ----
    for (int r = warp; r < 38; r += 8) {
        int gy = (y0 + r - 3) & 511;
        const float* rowp = base + (size_t)gy * (Wv * 3);
        int gx0 = (x0 + lane - 3) & 511;
        si[r * SW + lane] = __ldg(rowp + gx0 * 3);
        if (lane < 6) {
            int gx1 = (x0 + lane + 29) & 511;
            si[r * SW + lane + 32] = __ldg(rowp + gx1 * 3);
        }
    }
    __syncthreads();

    // ---- packed blur: 18 chunks x 18 pair-cols, 2 rows per task ------------
    // Taps built from identical smem values in identical order -> bit-identical.
    {
        const uint64_t W1 = dupc(0.0625f), W2 = dupc(0.125f), W4 = dupc(0.25f);
        for (int j = tid; j < 18 * 18; j += 256) {
            int ch = j / 18, pc = j - ch * 18;
            int r0 = ch * 2;                      // output rows r0, r0+1 (<=35)
            const float* p = &si[r0 * SW + 2 * pc];
            uint64_t A0, B0, C0, A1, B1, C1, A2, B2, C2, A3, B3, C3;
            load3(p,          A0, B0, C0);
            load3(p + SW,     A1, B1, C1);
            load3(p + 2 * SW, A2, B2, C2);
            load3(p + 3 * SW, A3, B3, C3);
            {
                uint64_t t[9] = { mul2(A0, W1), mul2(B0, W2), mul2(C0, W1),
                                  mul2(A1, W2), mul2(B1, W4), mul2(C1, W2),
                                  mul2(A2, W1), mul2(B2, W2), mul2(C2, W1) };
                *(uint64_t*)&sl[r0 * SW + 2 * pc] = sum_exact2<9>(t);
            }
            {
                uint64_t t[9] = { mul2(A1, W1), mul2(B1, W2), mul2(C1, W1),
                                  mul2(A2, W2), mul2(B2, W4), mul2(C2, W2),
                                  mul2(A3, W1), mul2(B3, W2), mul2(C3, W1) };
                *(uint64_t*)&sl[(r0 + 1) * SW + 2 * pc] = sum_exact2<9>(t);
            }
        }
    }
    // ---- border fixup: recompute blur at cells whose REAL coord is on an
    //      image boundary line (the only cells where zero-pad masks act) ----
    if (border) {
        __syncthreads();
        for (int i = tid; i < 36 * 36; i += 256) {
            int r = i / 36, cc = i - r * 36;
            int py = (y0 + r - 2) & 511;
            int px = (x0 + cc - 2) & 511;
            bool edge = (py == 0) | (py == 511) | (px == 0) | (px == 511);
            if (edge) {
                int ii = (r + 1) * SW + (cc + 1);
                float t[9];
                int k = 0;
#pragma unroll
                for (int dy = -1; dy <= 1; ++dy) {
                    bool yok = (unsigned)(py + dy) < 512u;
#pragma unroll
                    for (int dx = -1; dx <= 1; ++dx) {
                        bool ok = yok && ((unsigned)(px + dx) < 512u);
                        float v = ok ? si[ii + dy * SW + dx] : 0.f;
                        float w = (dy == 0) ? ((dx == 0) ? 0.25f : 0.125f)
                                            : ((dx == 0) ? 0.125f : 0.0625f);
                        t[k++] = __fmul_rn(v, w);
                    }
                }
                sl[r * SW + cc] = sum_exact<9>(t);
            }
        }
    }
    __syncthreads();

    // ---- packed sobel + mag + sector: 17 chunks x 17 pair-cols, 2 rows/task --
    {
        const uint64_t M2 = dupc(-2.f), P2 = dupc(2.f);
        for (int j = tid; j < 17 * 17; j += 256) {
            int ch = j / 17, pc = j - ch * 17;
            int r0 = ch * 2;                      // output rows r0, r0+1 (<=33)
            const float* p = &sl[r0 * SW + 2 * pc];
            uint64_t A0, B0, C0, A1, B1, C1, A2, B2, C2, A3, B3, C3;
            load3(p,          A0, B0, C0);
            load3(p + SW,     A1, B1, C1);
            load3(p + 2 * SW, A2, B2, C2);
            load3(p + 3 * SW, A3, B3, C3);
#pragma unroll
            for (int i = 0; i < 2; ++i) {
                uint64_t gxp, gyp;
                if (i == 0) sobel_pair(A0, B0, C0, A1, C1, A2, B2, C2, M2, P2, gxp, gyp);
                else        sobel_pair(A1, B1, C1, A2, C2, A3, B3, C3, M2, P2, gxp, gyp);
                int rr = r0 + i;
                uint64_t s2 = add2(mul2(gxp, gxp), mul2(gyp, gyp));
                float s0, s1;
                upk2(s2, s0, s1);
                *(uint64_t*)&sm[rr * SW + 2 * pc] = pk2(__fsqrt_rn(s0), __fsqrt_rn(s1));
                if (rr >= 1 && rr <= 32) {
                    float gx0, gx1, gy0, gy1;
                    upk2(gxp, gx0, gx1);
                    upk2(gyp, gy0, gy1);
                    int c0 = 2 * pc;
                    if (c0 >= 1 && c0 <= 32) ssec[(rr - 1) * 32 + c0 - 1] = sector_of(gx0, gy0);
                    if (c0 + 1 <= 32)        ssec[(rr - 1) * 32 + c0]     = sector_of(gx1, gy1);
                }
            }
        }
    }
    // ---- border fixup for sobel/mag/sector on boundary-line centers ----
    if (border) {
        __syncthreads();
        for (int i = tid; i < 34 * 34; i += 256) {
            int r = i / 34, cc = i - r * 34;
            int my = (y0 + r - 1) & 511;
            int mx = (x0 + cc - 1) & 511;
            bool edge = (my == 0) | (my == 511) | (mx == 0) | (mx == 511);
            if (edge) {
                int bi = (r + 1) * SW + (cc + 1);
                float gxv, gyv;
                sobel_masked(sl, bi, my > 0, my < 511, mx > 0, mx < 511, gxv, gyv);
                sm[r * SW + cc] = mag_of(gxv, gyv);
                if (r >= 1 && r <= 32 && cc >= 1 && cc <= 32)
                    ssec[(r - 1) * 32 + (cc - 1)] = sector_of(gxv, gyv);
            }
        }
    }
    __syncthreads();

    // ---- NMS + double threshold; ballot into bit planes ----
#pragma unroll
    for (int k = 0; k < 4; ++k) {
        int row = warp + k * 8;                 // 0..31
        int mi = (row + 1) * SW + (lane + 1);
        float m = sm[mi];
        uint8_t s = ssec[row * 32 + lane];
        int off = (int)((0x29282701u >> (s << 3)) & 0xFFu);   // {1,39,40,41}
        float na = sm[mi + off];
        float nb = sm[mi - off];
        float sup = (m >= na && m >= nb) ? m : 0.f;
        bool strong = sup >= 0.3f;
        bool weak   = (sup >= 0.1f) && !strong;
        uint32_t wbal = __ballot_sync(0xFFFFFFFFu, weak);
        uint32_t sbal = __ballot_sync(0xFFFFFFFFu, strong);
        if (lane == 0) {
            int idx = ((plane << 9) + y0 + row) * 16 + (x0 >> 5);
            g_weakbits[idx] = wbal;
            g_strongbits[idx] = sbal;
        }
    }
}

// ============================ K3: hysteresis on bitboards ====================
__device__ __forceinline__ void hexpand8(const uint64_t* S, uint64_t* E) {
#pragma unroll
    for (int j = 0; j < 8; ++j) {
        uint64_t s = S[j];
        uint64_t l = (s << 1) | (S[(j + 7) & 7] >> 63);   // neighbor x-1
        uint64_t r = (s >> 1) | (S[(j + 1) & 7] << 63);   // neighbor x+1
        E[j] = s | l | r;
    }
}

__device__ __forceinline__ void row_closure(uint64_t* S, const uint64_t* W) {
    for (;;) {
        uint64_t E[8];
        hexpand8(S, E);
        uint64_t any = 0;
#pragma unroll
        for (int j = 0; j < 8; ++j) {
            uint64_t n = W[j] & E[j] & ~S[j];
            any |= n;
            S[j] |= n;
        }
        if (!any) break;
    }
}

__global__ void __launch_bounds__(512) hyst_k() {
    __shared__ uint64_t H[512][8];
    int row = threadIdx.x;          // one row per thread
    int plane = blockIdx.x;
    int base = ((plane << 9) + row) * 16;

    uint64_t S[8], W[8];
#pragma unroll
    for (int j = 0; j < 8; ++j) {
        S[j] = (uint64_t)g_strongbits[base + 2 * j] |
               ((uint64_t)g_strongbits[base + 2 * j + 1] << 32);
        W[j] = (uint64_t)g_weakbits[base + 2 * j] |
               ((uint64_t)g_weakbits[base + 2 * j + 1] << 32);
    }
    row_closure(S, W);

    int up = (row + 511) & 511;
    int dn = (row + 1) & 511;

    for (;;) {
        uint64_t E[8];
        hexpand8(S, E);
#pragma unroll
        for (int j = 0; j < 8; ++j) H[row][j] = E[j];
        __syncthreads();
        uint64_t any = 0;
#pragma unroll
        for (int j = 0; j < 8; ++j) {
            uint64_t n = W[j] & (H[up][j] | H[dn][j]) & ~S[j];
            any |= n;
            S[j] |= n;
        }
        if (any) row_closure(S, W);
        if (!__syncthreads_or(any != 0)) break;
    }

#pragma unroll
    for (int j = 0; j < 8; ++j) {
        g_strongbits[base + 2 * j]     = (uint32_t)S[j];
        g_strongbits[base + 2 * j + 1] = (uint32_t)(S[j] >> 32);
    }
}

// ============================ K4: expand strong bits -> f32 NHWC (vec4) ======
__global__ void __launch_bounds__(384) out_k(float4* __restrict__ out) {
    __shared__ uint32_t srow[48];     // 3 channels x 16 words for this (b,y) row
    int rowid = blockIdx.x;           // 0..8191 = b*512 + y
    int b = rowid >> 9, y = rowid & 511;
    int tid = threadIdx.x;
    if (tid < 48) {
        int c = tid >> 4, w = tid & 15;
        srow[tid] = g_strongbits[(((b * 3 + c) << 9) + y) * 16 + w];
    }
    __syncthreads();
    int e = tid * 4;                  // element within the 1536-float row
    float4 v;
    float* vp = (float*)&v;
#pragma unroll
    for (int k = 0; k < 4; ++k) {
        int ee = e + k;
        int xx = (ee * 21846) >> 16;  // ee/3 for ee < 32768
        int c  = ee - 3 * xx;
        vp[k] = ((srow[(c << 4) + (xx >> 5)] >> (xx & 31)) & 1u) ? 1.f : 0.f;
    }
    out[(size_t)rowid * 384 + tid] = v;
}

// --------------------------------------------------------------- launch
extern "C" void kernel_launch(void* const* d_in, const int* in_sizes, int n_in,
                              void* d_out, int out_size) {
    const float* x = (const float*)d_in[0];

    dim3 g1(NPLANES, Wv / 32, Hv / 32);   // plane fastest -> channel L2 reuse
    canny_k<<<g1, 256>>>(x);

    hyst_k<<<NPLANES, 512>>>();

    out_k<<<Bv * Hv, 384>>>((float4*)d_out);
}

// round 11
// speedup vs baseline: 1.1391x; 1.1391x over previous
#include <cuda_runtime.h>
#include <stdint.h>
#include <math.h>

#define Bv 16
#define Hv 512
#define Wv 512
#define NPLANES 48

// Scratch (device globals -- no runtime allocation allowed)
__device__ uint32_t g_weakbits[NPLANES * Hv * 16];    // 16 u32 words per row
__device__ uint32_t g_strongbits[NPLANES * Hv * 16];

// ---------------- scalar error-free compensated summation --------------------
__device__ __forceinline__ void two_sum(float a, float b, float& s, float& e) {
    s = __fadd_rn(a, b);
    float bb = __fsub_rn(s, a);
    e = __fadd_rn(__fsub_rn(a, __fsub_rn(s, bb)), __fsub_rn(b, bb));
}

template <int N>
__device__ __forceinline__ float sum_exact(const float* t) {
    float s = t[0], e = 0.f;
#pragma unroll
    for (int i = 1; i < N; ++i) {
        float ei;
        two_sum(s, t[i], s, ei);
        e = __fadd_rn(e, ei);
    }
    return __fadd_rn(s, e);
}

// ---------------- packed f32x2 primitives (per-lane IEEE RN: bit-identical) --
__device__ __forceinline__ uint64_t pk2(float lo, float hi) {
    uint64_t r; asm("mov.b64 %0, {%1,%2};" : "=l"(r) : "f"(lo), "f"(hi)); return r;
}
__device__ __forceinline__ void upk2(uint64_t v, float& lo, float& hi) {
    asm("mov.b64 {%0,%1}, %2;" : "=f"(lo), "=f"(hi) : "l"(v));
}
__device__ __forceinline__ uint64_t dupc(float w) {
    uint32_t u = __float_as_uint(w);
    return ((uint64_t)u << 32) | u;
}
__device__ __forceinline__ uint64_t add2(uint64_t a, uint64_t b) {
    uint64_t r; asm("add.rn.f32x2 %0, %1, %2;" : "=l"(r) : "l"(a), "l"(b)); return r;
}
__device__ __forceinline__ uint64_t mul2(uint64_t a, uint64_t b) {
    uint64_t r; asm("mul.rn.f32x2 %0, %1, %2;" : "=l"(r) : "l"(a), "l"(b)); return r;
}
__device__ __forceinline__ uint64_t fma2(uint64_t a, uint64_t b, uint64_t c) {
    uint64_t r; asm("fma.rn.f32x2 %0, %1, %2, %3;" : "=l"(r) : "l"(a), "l"(b), "l"(c)); return r;
}
// exact: fma(b,-1,a) rounds a-b once -> identical to sub.rn per lane
__device__ __forceinline__ uint64_t sub2(uint64_t a, uint64_t b) {
    return fma2(b, 0xBF800000BF800000ULL, a);
}
__device__ __forceinline__ uint64_t neg2(uint64_t a) {        // exact negation
    return mul2(a, 0xBF800000BF800000ULL);
}
__device__ __forceinline__ void two_sum2(uint64_t a, uint64_t b, uint64_t& s, uint64_t& e) {
    s = add2(a, b);
    uint64_t bb = sub2(s, a);
    uint64_t t1 = sub2(s, bb);
    uint64_t t2 = sub2(a, t1);
    uint64_t t3 = sub2(b, bb);
    e = add2(t2, t3);
}
template <int N>
__device__ __forceinline__ uint64_t sum_exact2(const uint64_t* t) {
    uint64_t s = t[0], e = 0ULL;   // 0.0f packed
#pragma unroll
    for (int i = 1; i < N; ++i) {
        uint64_t ei;
        two_sum2(s, t[i], s, ei);
        e = add2(e, ei);
    }
    return add2(s, e);
}

// load 4 consecutive floats (8B-aligned) -> tap pairs A=(v0,v1) B=(v1,v2) C=(v2,v3)
__device__ __forceinline__ void load3(const float* p, uint64_t& A, uint64_t& B, uint64_t& C) {
    A = *(const uint64_t*)p;
    C = *(const uint64_t*)(p + 2);
    float a0, a1, c0, c1;
    upk2(A, a0, a1);
    upk2(C, c0, c1);
    B = pk2(a1, c0);
}

// ---------------- sector from slopes (no atan2; boundaries from 180/3.14159) -
#define SEC_T1  0.41421317f
#define SEC_T2  2.4142068f
#define SEC_TP3 2.4142249f
#define SEC_TP4 0.41421628f

__device__ __forceinline__ uint8_t sector_of(float gx, float gy) {
    if (gy >= 0.f) {
        if (gx > 0.f)  return (gy <= SEC_T1 * gx) ? 0 : ((gy <= SEC_T2 * gx) ? 1 : 2);
        if (gx < 0.f) { float a = -gx;
                        return (gy < SEC_TP4 * a) ? 0 : ((gy < SEC_TP3 * a) ? 3 : 2); }
        return (gy > 0.f) ? 2 : 0;
    } else {
        float g = -gy;
        if (gx > 0.f)  return (g < SEC_T1 * gx) ? 0 : ((g < SEC_T2 * gx) ? 3 : 2);
        if (gx < 0.f) { float a = -gx;
                        return (g <= SEC_TP4 * a) ? 0 : ((g <= SEC_TP3 * a) ? 1 : 2); }
        return 2;
    }
}

// ========== K1: blur + sobel + mag + sector + NMS + threshold (fused) ========
// Tile: 64x32 inner pixels, 512 threads. Same per-task inner code as the
// 30-reg R9 version (one pair-cell per task) -- only geometry changed.
#define SW 72   // smem row stride (floats); even -> 8B-aligned pair addresses

__device__ __forceinline__ void sobel_masked(const float* sb, int bi,
                                             bool ym, bool yp, bool xm, bool xp,
                                             float& gx, float& gy) {
    float v00 = (ym && xm) ? sb[bi - SW - 1] : 0.f;
    float v01 =  ym        ? sb[bi - SW]     : 0.f;
    float v02 = (ym && xp) ? sb[bi - SW + 1] : 0.f;
    float v10 =  xm        ? sb[bi - 1]      : 0.f;
    float v12 =  xp        ? sb[bi + 1]      : 0.f;
    float v20 = (yp && xm) ? sb[bi + SW - 1] : 0.f;
    float v21 =  yp        ? sb[bi + SW]     : 0.f;
    float v22 = (yp && xp) ? sb[bi + SW + 1] : 0.f;
    float tx[6] = { -v00, v02, __fmul_rn(-2.f, v10), __fmul_rn(2.f, v12), -v20, v22 };
    gx = sum_exact<6>(tx);
    float ty[6] = { -v00, __fmul_rn(-2.f, v01), -v02, v20, __fmul_rn(2.f, v21), v22 };
    gy = sum_exact<6>(ty);
}

__device__ __forceinline__ float mag_of(float gx, float gy) {
    float s = __fadd_rn(__fmul_rn(gx, gx), __fmul_rn(gy, gy));
    return __fsqrt_rn(s);
}

__global__ void __launch_bounds__(512) canny_k(const float* __restrict__ x) {
    __shared__ __align__(16) float   si[38 * SW];   // input  rows y0-3..y0+34 (toroidal)
    __shared__ __align__(16) float   sl[36 * SW];   // blur   y0-2..y0+33
    __shared__ __align__(16) float   sm[34 * SW];   // mag    y0-1..y0+32
    __shared__ uint8_t ssec[32 * 64];               // sector of inner pixels
    int tid  = threadIdx.x;
    int lane = tid & 31;
    int warp = tid >> 5;                            // 0..15
    int plane = blockIdx.x;                 // b*3+c (fastest -> channel L2 reuse)
    int x0 = blockIdx.y * 64;
    int y0 = blockIdx.z * 32;
    int b = plane / 3, c = plane - 3 * b;
    const float* base = x + (size_t)b * (Hv * Wv * 3) + c;

    bool border = (blockIdx.y == 0) || (blockIdx.y == 7) ||
                  (blockIdx.z == 0) || (blockIdx.z == 15);

    // ---- load 38x70 input (toroidal; interior blocks never actually wrap) ----
    for (int r = warp; r < 38; r += 16) {
        int gy = (y0 + r - 3) & 511;
        const float* rowp = base + (size_t)gy * (Wv * 3);
        int gx0 = (x0 + lane - 3) & 511;
        si[r * SW + lane] = __ldg(rowp + gx0 * 3);
        int gx1 = (x0 + lane + 29) & 511;
        si[r * SW + lane + 32] = __ldg(rowp + gx1 * 3);
        if (lane < 6) {
            int gx2 = (x0 + lane + 61) & 511;
            si[r * SW + lane + 64] = __ldg(rowp + gx2 * 3);
        }
    }
    __syncthreads();

    // ---- packed blur: 36 rows x 34 pair-cols (no masks; wrap-conv values) ----
    {
        const uint64_t W1 = dupc(0.0625f), W2 = dupc(0.125f), W4 = dupc(0.25f);
        for (int j = tid; j < 36 * 34; j += 512) {
            int r = j / 34, p = j - r * 34;
            int bofs = r * SW + 2 * p;
            uint64_t A0, B0, C0, A1, B1, C1, A2, B2, C2;
            load3(&si[bofs],          A0, B0, C0);
            load3(&si[bofs + SW],     A1, B1, C1);
            load3(&si[bofs + 2 * SW], A2, B2, C2);
            uint64_t t[9] = { mul2(A0, W1), mul2(B0, W2), mul2(C0, W1),
                              mul2(A1, W2), mul2(B1, W4), mul2(C1, W2),
                              mul2(A2, W1), mul2(B2, W2), mul2(C2, W1) };
            *(uint64_t*)&sl[r * SW + 2 * p] = sum_exact2<9>(t);
        }
    }
    // ---- border fixup: recompute blur at cells whose REAL coord is on an
    //      image boundary line (the only cells where zero-pad masks act) ----
    if (border) {
        __syncthreads();
        for (int i = tid; i < 36 * 68; i += 512) {
            int r = i / 68, cc = i - r * 68;
            int py = (y0 + r - 2) & 511;
            int px = (x0 + cc - 2) & 511;
            bool edge = (py == 0) | (py == 511) | (px == 0) | (px == 511);
            if (edge) {
                int ii = (r + 1) * SW + (cc + 1);
                float t[9];
                int k = 0;
#pragma unroll
                for (int dy = -1; dy <= 1; ++dy) {
                    bool yok = (unsigned)(py + dy) < 512u;
#pragma unroll
                    for (int dx = -1; dx <= 1; ++dx) {
                        bool ok = yok && ((unsigned)(px + dx) < 512u);
                        float v = ok ? si[ii + dy * SW + dx] : 0.f;
                        float w = (dy == 0) ? ((dx == 0) ? 0.25f : 0.125f)
                                            : ((dx == 0) ? 0.125f : 0.0625f);
                        t[k++] = __fmul_rn(v, w);
                    }
                }
                sl[r * SW + cc] = sum_exact<9>(t);
            }
        }
    }
    __syncthreads();

    // ---- packed sobel + mag + sector: 34 rows x 33 pair-cols ----
    {
        const uint64_t M2 = dupc(-2.f), P2 = dupc(2.f);
        for (int j = tid; j < 34 * 33; j += 512) {
            int r = j / 33, p = j - r * 33;
            int bofs = r * SW + 2 * p;
            uint64_t A0, B0, C0, A1, B1, C1, A2, B2, C2;
            load3(&sl[bofs],          A0, B0, C0);
            load3(&sl[bofs + SW],     A1, B1, C1);
            load3(&sl[bofs + 2 * SW], A2, B2, C2);
            uint64_t tx[6] = { neg2(A0), C0, mul2(A1, M2), mul2(C1, P2), neg2(A2), C2 };
            uint64_t gxp = sum_exact2<6>(tx);
            uint64_t ty[6] = { neg2(A0), mul2(B0, M2), neg2(C0), A2, mul2(B2, P2), C2 };
            uint64_t gyp = sum_exact2<6>(ty);

            uint64_t s2 = add2(mul2(gxp, gxp), mul2(gyp, gyp));
            float s0, s1;
            upk2(s2, s0, s1);
            *(uint64_t*)&sm[r * SW + 2 * p] = pk2(__fsqrt_rn(s0), __fsqrt_rn(s1));

            if (r >= 1 && r <= 32) {
                float gx0, gx1, gy0, gy1;
                upk2(gxp, gx0, gx1);
                upk2(gyp, gy0, gy1);
                int c0 = 2 * p;
                if (c0 >= 1 && c0 <= 64) ssec[(r - 1) * 64 + c0 - 1] = sector_of(gx0, gy0);
                if (c0 + 1 <= 64)        ssec[(r - 1) * 64 + c0]     = sector_of(gx1, gy1);
            }
        }
    }
    // ---- border fixup for sobel/mag/sector on boundary-line centers ----
    if (border) {
        __syncthreads();
        for (int i = tid; i < 34 * 66; i += 512) {
            int r = i / 66, cc = i - r * 66;
            int my = (y0 + r - 1) & 511;
            int mx = (x0 + cc - 1) & 511;
            bool edge = (my == 0) | (my == 511) | (mx == 0) | (mx == 511);
            if (edge) {
                int bi = (r + 1) * SW + (cc + 1);
                float gxv, gyv;
                sobel_masked(sl, bi, my > 0, my < 511, mx > 0, mx < 511, gxv, gyv);
                sm[r * SW + cc] = mag_of(gxv, gyv);
                if (r >= 1 && r <= 32 && cc >= 1 && cc <= 64)
                    ssec[(r - 1) * 64 + (cc - 1)] = sector_of(gxv, gyv);
            }
        }
    }
    __syncthreads();

    // ---- NMS + double threshold; ballot into bit planes ----
#pragma unroll
    for (int k = 0; k < 4; ++k) {
        int p = k * 512 + tid;                 // 0..2047
        int row = p >> 6;                      // 0..31
        int xx = p & 63;                       // 0..63; (xx & 31) == lane
        int mi = (row + 1) * SW + (xx + 1);
        float m = sm[mi];
        uint8_t s = ssec[row * 64 + xx];
        int off = (int)((0x49484701u >> (s << 3)) & 0xFFu);   // {1,71,72,73}
        float na = sm[mi + off];
        float nb = sm[mi - off];
        float sup = (m >= na && m >= nb) ? m : 0.f;
        bool strong = sup >= 0.3f;
        bool weak   = (sup >= 0.1f) && !strong;
        uint32_t wbal = __ballot_sync(0xFFFFFFFFu, weak);
        uint32_t sbal = __ballot_sync(0xFFFFFFFFu, strong);
        if (lane == 0) {
            int idx = ((plane << 9) + y0 + row) * 16 + (x0 >> 5) + (xx >> 5);
            g_weakbits[idx] = wbal;
            g_strongbits[idx] = sbal;
        }
    }
}

// ============================ K3: hysteresis on bitboards ====================
__device__ __forceinline__ void hexpand8(const uint64_t* S, uint64_t* E) {
#pragma unroll
    for (int j = 0; j < 8; ++j) {
        uint64_t s = S[j];
        uint64_t l = (s << 1) | (S[(j + 7) & 7] >> 63);   // neighbor x-1
        uint64_t r = (s >> 1) | (S[(j + 1) & 7] << 63);   // neighbor x+1
        E[j] = s | l | r;
    }
}

__device__ __forceinline__ void row_closure(uint64_t* S, const uint64_t* W) {
    for (;;) {
        uint64_t E[8];
        hexpand8(S, E);
        uint64_t any = 0;
#pragma unroll
        for (int j = 0; j < 8; ++j) {
            uint64_t n = W[j] & E[j] & ~S[j];
            any |= n;
            S[j] |= n;
        }
        if (!any) break;
    }
}

__global__ void __launch_bounds__(512) hyst_k() {
    __shared__ uint64_t H[512][8];
    int row = threadIdx.x;          // one row per thread
    int plane = blockIdx.x;
    int base = ((plane << 9) + row) * 16;

    uint64_t S[8], W[8];
#pragma unroll
    for (int j = 0; j < 8; ++j) {
        S[j] = (uint64_t)g_strongbits[base + 2 * j] |
               ((uint64_t)g_strongbits[base + 2 * j + 1] << 32);
        W[j] = (uint64_t)g_weakbits[base + 2 * j] |
               ((uint64_t)g_weakbits[base + 2 * j + 1] << 32);
    }
    row_closure(S, W);

    int up = (row + 511) & 511;
    int dn = (row + 1) & 511;

    for (;;) {
        uint64_t E[8];
        hexpand8(S, E);
#pragma unroll
        for (int j = 0; j < 8; ++j) H[row][j] = E[j];
        __syncthreads();
        uint64_t any = 0;
#pragma unroll
        for (int j = 0; j < 8; ++j) {
            uint64_t n = W[j] & (H[up][j] | H[dn][j]) & ~S[j];
            any |= n;
            S[j] |= n;
        }
        if (any) row_closure(S, W);
        if (!__syncthreads_or(any != 0)) break;
    }

#pragma unroll
    for (int j = 0; j < 8; ++j) {
        g_strongbits[base + 2 * j]     = (uint32_t)S[j];
        g_strongbits[base + 2 * j + 1] = (uint32_t)(S[j] >> 32);
    }
}

// ============================ K4: expand strong bits -> f32 NHWC (vec4) ======
__global__ void __launch_bounds__(384) out_k(float4* __restrict__ out) {
    __shared__ uint32_t srow[48];     // 3 channels x 16 words for this (b,y) row
    int rowid = blockIdx.x;           // 0..8191 = b*512 + y
    int b = rowid >> 9, y = rowid & 511;
    int tid = threadIdx.x;
    if (tid < 48) {
        int c = tid >> 4, w = tid & 15;
        srow[tid] = g_strongbits[(((b * 3 + c) << 9) + y) * 16 + w];
    }
    __syncthreads();
    int e = tid * 4;                  // element within the 1536-float row
    float4 v;
    float* vp = (float*)&v;
#pragma unroll
    for (int k = 0; k < 4; ++k) {
        int ee = e + k;
        int xx = (ee * 21846) >> 16;  // ee/3 for ee < 32768
        int c  = ee - 3 * xx;
        vp[k] = ((srow[(c << 4) + (xx >> 5)] >> (xx & 31)) & 1u) ? 1.f : 0.f;
    }
    out[(size_t)rowid * 384 + tid] = v;
}

// --------------------------------------------------------------- launch
extern "C" void kernel_launch(void* const* d_in, const int* in_sizes, int n_in,
                              void* d_out, int out_size) {
    const float* x = (const float*)d_in[0];

    dim3 g1(NPLANES, Wv / 64, Hv / 32);   // plane fastest -> channel L2 reuse
    canny_k<<<g1, 512>>>(x);

    hyst_k<<<NPLANES, 512>>>();

    out_k<<<Bv * Hv, 384>>>((float4*)d_out);
}